// round 15
// baseline (speedup 1.0000x reference)
#include <cuda_runtime.h>
#include <cuda_bf16.h>
#include <cstdint>

#define NLEAF 4096
#define NNODE 8191
#define NROW  8192
#define HID   512

#define OFF_EF     16382
#define OFF_EMB    16807932
#define OFF_FOCAL  21002236

// ----------------------------- scratch ---------------------------------------
__device__ float g_dW[NROW*HID];
__device__ float g_h[NROW*HID];
__device__ float g_cvec[HID];
__device__ float g_hf[HID];
__device__ float g_c[NNODE];
__device__ int   g_postF[NNODE];
__device__ int   g_preF[NNODE];

// int8x2 quantized operands (GEMM0/GEMM1)
__device__ int8_t gAq1[(size_t)NROW*1024];
__device__ int8_t gAq2[(size_t)NROW*1024];
__device__ int8_t gB0q1[(size_t)512*512];
__device__ int8_t gB0q2[(size_t)512*512];
__device__ int8_t gB1q1[(size_t)512*1024];
__device__ int8_t gB1q2[(size_t)512*1024];
__device__ float  g_sA[NROW];
__device__ float  g_sB0[512];
__device__ float  g_sB1[512];

// bf16 split operands (GEMM2)
__device__ __nv_bfloat16 gZ_hi[(size_t)NROW*512];
__device__ __nv_bfloat16 gZ_lo[(size_t)NROW*512];
__device__ __nv_bfloat16 gB2_hi[(size_t)512*1024];
__device__ __nv_bfloat16 gB2_lo[(size_t)512*1024];

// ----------------------------- helpers ----------------------------------------
__device__ __forceinline__ void st_rel(int* p, int v) {
    asm volatile("st.release.gpu.global.b32 [%0], %1;" :: "l"(p), "r"(v) : "memory");
}
__device__ __forceinline__ int ld_acq(const int* p) {
    int v;
    asm volatile("ld.acquire.gpu.global.b32 %0, [%1];" : "=r"(v) : "l"(p) : "memory");
    return v;
}
__device__ __forceinline__ void split_bf(float v, __nv_bfloat16 &h, __nv_bfloat16 &l) {
    h = __float2bfloat16(v);
    l = __float2bfloat16(v - __bfloat162float(h));
}
__device__ __forceinline__ float eluf(float x) { return x > 0.f ? x : expm1f(x); }

__device__ __forceinline__ void mma_bf16(float* d, const uint32_t* a, uint32_t b0, uint32_t b1) {
    asm volatile(
        "mma.sync.aligned.m16n8k16.row.col.f32.bf16.bf16.f32 "
        "{%0,%1,%2,%3}, {%4,%5,%6,%7}, {%8,%9}, {%0,%1,%2,%3};"
        : "+f"(d[0]), "+f"(d[1]), "+f"(d[2]), "+f"(d[3])
        : "r"(a[0]), "r"(a[1]), "r"(a[2]), "r"(a[3]), "r"(b0), "r"(b1));
}
__device__ __forceinline__ void mma_s8(int* d, const uint32_t* a, uint32_t b0, uint32_t b1) {
    asm volatile(
        "mma.sync.aligned.m16n8k32.row.col.s32.s8.s8.s32 "
        "{%0,%1,%2,%3}, {%4,%5,%6,%7}, {%8,%9}, {%0,%1,%2,%3};"
        : "+r"(d[0]), "+r"(d[1]), "+r"(d[2]), "+r"(d[3])
        : "r"(a[0]), "r"(a[1]), "r"(a[2]), "r"(a[3]), "r"(b0), "r"(b1));
}
__device__ __forceinline__ void ldm_x4(uint32_t* r, uint32_t saddr) {
    asm volatile("ldmatrix.sync.aligned.m8n8.x4.shared.b16 {%0,%1,%2,%3}, [%4];"
        : "=r"(r[0]), "=r"(r[1]), "=r"(r[2]), "=r"(r[3]) : "r"(saddr));
}
__device__ __forceinline__ void cp16(uint32_t dst, const void* src) {
    asm volatile("cp.async.cg.shared.global [%0], [%1], 16;" :: "r"(dst), "l"(src));
}
__device__ __forceinline__ void quant2(float x, float s, float inv_s, int8_t &q1, int8_t &q2) {
    int i1 = __float2int_rn(x * inv_s);
    float r = x - s * (float)i1;
    int i2 = __float2int_rn(r * inv_s * 128.f);
    q1 = (int8_t)i1; q2 = (int8_t)i2;
}

// ----------------------------- launch 1: prep ---------------------------------
// b<512: quantize W2 col n -> gB0 ; b<64 also resets flags + logits init
// b in [512,1024): bf16-split Wh2 -> gB2
// b>=1024: leaf-row init (+focal)
__global__ void k_prep(const float* __restrict__ W2, const float* __restrict__ Wh2,
                       const int* __restrict__ ns, const int* __restrict__ focal,
                       const float* __restrict__ W1, const float* __restrict__ bh3,
                       float* __restrict__ out) {
    int b = blockIdx.x;
    int tid = threadIdx.x;
    if (b < 512) {
        __shared__ float red[256];
        if (b < 64) {
            int i = b*256 + tid;
            if (i < NNODE) { g_postF[i] = 0; out[i] = bh3[0]; }
            else if (i < 2*NNODE) g_preF[i - NNODE] = 0;
        }
        int n = b;
        float v[2];
        float mx = 0.f;
        #pragma unroll
        for (int it = 0; it < 2; it++) {
            v[it] = W2[(size_t)(tid + 256*it)*512 + n];
            mx = fmaxf(mx, fabsf(v[it]));
        }
        red[tid] = mx; __syncthreads();
        for (int st = 128; st; st >>= 1) {
            if (tid < st) red[tid] = fmaxf(red[tid], red[tid + st]);
            __syncthreads();
        }
        float s = fmaxf(red[0], 1e-30f) / 127.f;
        float inv_s = 1.f / s;
        #pragma unroll
        for (int it = 0; it < 2; it++) {
            int k = tid + 256*it;
            int8_t q1, q2; quant2(v[it], s, inv_s, q1, q2);
            gB0q1[(size_t)n*512 + k] = q1;
            gB0q2[(size_t)n*512 + k] = q2;
        }
        if (tid == 0) g_sB0[n] = s;
        return;
    }
    if (b < 1024) {
        int n = b - 512;
        for (int k = tid; k < 512; k += blockDim.x) {
            float v = Wh2[(size_t)k*512 + n];
            __nv_bfloat16 h, l; split_bf(v, h, l);
            gB2_hi[(size_t)n*1024 + k] = h;
            gB2_lo[(size_t)n*1024 + k] = l;
        }
        return;
    }
    int bb = b - 1024;                      // 0..4096
    int u, src;
    if (bb == NLEAF) { u = NNODE; src = focal[0]; }
    else {
        u = bb; src = ns[bb];
        if (tid == 0) out[OFF_FOCAL + bb] = (bb == focal[0]) ? 1.f : 0.f;
        if (src < 0) return;
    }
    if (tid < 128) {
        const float4* w = (const float4*)(W1 + (size_t)src*HID);
        float4* d = (float4*)(g_dW + (size_t)u*HID);
        d[tid] = w[tid];
    }
}

// ----------------------------- launch 2: tree + agg phase 0 -------------------
__global__ void k_tree(const int* __restrict__ ch0, const int* __restrict__ ch1,
                       const int* __restrict__ parent, const int* __restrict__ neigh,
                       const float* __restrict__ bias) {
    const int w    = blockIdx.x * (blockDim.x >> 5) + (threadIdx.x >> 5);
    const int lane = threadIdx.x & 31;
    const int NI   = NNODE - NLEAF;
    const int root = NNODE - 1;

    if (w < NI) {
        const int u = NLEAF + w;
        const int a = ch0[u], b = ch1[u];

        if (a >= NLEAF) while (!ld_acq(&g_postF[a])) { }
        if (b >= NLEAF) while (!ld_acq(&g_postF[b])) { }
        __syncwarp();
        float ca = __ldcg(&g_c[a]);
        float cb = __ldcg(&g_c[b]);
        float cu = 1.f / (3.f - ca - cb);
        const float4* pa = (const float4*)(g_dW + (size_t)a*HID);
        const float4* pb = (const float4*)(g_dW + (size_t)b*HID);
        float4*       pu = (float4*)(g_dW + (size_t)u*HID);
        #pragma unroll
        for (int j = 0; j < 4; j++) {
            int c4 = lane + j*32;
            float4 x = __ldcg(pa + c4), y = __ldcg(pb + c4), r;
            r.x = cu*(x.x+y.x); r.y = cu*(x.y+y.y);
            r.z = cu*(x.z+y.z); r.w = cu*(x.w+y.w);
            pu[c4] = r;
        }
        if (lane == 0) g_c[u] = cu;
        __threadfence();
        __syncwarp();
        if (lane == 0) {
            st_rel(&g_postF[u], 1);
            if (u == root) st_rel(&g_preF[u], 1);
        }
        __syncwarp();

        if (u != root) {
            const int p = parent[u];
            while (!ld_acq(&g_preF[p])) { }
            __syncwarp();
            const float4* pp = (const float4*)(g_dW + (size_t)p*HID);
            #pragma unroll
            for (int j = 0; j < 4; j++) {
                int c4 = lane + j*32;
                float4 x = __ldcg(pp + c4);
                float4 r = pu[c4];
                r.x += cu*x.x; r.y += cu*x.y; r.z += cu*x.z; r.w += cu*x.w;
                pu[c4] = r;
            }
            __threadfence();
            __syncwarp();
            if (lane == 0) st_rel(&g_preF[u], 1);
            __syncwarp();
        }
    }

    // ---- agg phase 0: rows 2w, 2w+1 ----
    #pragma unroll
    for (int q = 0; q < 2; q++) {
        int rrow = 2*w + q;
        int n0 = neigh[3*rrow], n1 = neigh[3*rrow+1], n2 = neigh[3*rrow+2];
        if (lane == 0) {
            if (rrow >= NLEAF && rrow < NNODE) while (!ld_acq(&g_preF[rrow])) { }
            if (n0 >= NLEAF && n0 < NNODE)     while (!ld_acq(&g_preF[n0])) { }
            if (n1 >= NLEAF && n1 < NNODE)     while (!ld_acq(&g_preF[n1])) { }
            if (n2 >= NLEAF && n2 < NNODE)     while (!ld_acq(&g_preF[n2])) { }
        }
        __syncwarp();
        float inv = 1.f / (1.f + (n0 >= 0) + (n1 >= 0) + (n2 >= 0));
        const float4* s  = (const float4*)(g_dW + (size_t)rrow*HID);
        const float4* p0 = (const float4*)(g_dW + (size_t)(n0 >= 0 ? n0 : 0)*HID);
        const float4* p1 = (const float4*)(g_dW + (size_t)(n1 >= 0 ? n1 : 0)*HID);
        const float4* p2 = (const float4*)(g_dW + (size_t)(n2 >= 0 ? n2 : 0)*HID);
        float4* dst = (float4*)(g_h + (size_t)rrow*HID);
        const float4* bb4 = (const float4*)bias;
        #pragma unroll
        for (int j4 = 0; j4 < 4; j4++) {
            int j = lane + j4*32;
            float4 v = __ldcg(s + j);
            if (n0 >= 0) { float4 t = __ldcg(p0 + j); v.x += t.x; v.y += t.y; v.z += t.z; v.w += t.w; }
            if (n1 >= 0) { float4 t = __ldcg(p1 + j); v.x += t.x; v.y += t.y; v.z += t.z; v.w += t.w; }
            if (n2 >= 0) { float4 t = __ldcg(p2 + j); v.x += t.x; v.y += t.y; v.z += t.z; v.w += t.w; }
            float4 bv = bb4[j];
            v.x = fmaxf(v.x*inv + bv.x, 0.f); v.y = fmaxf(v.y*inv + bv.y, 0.f);
            v.z = fmaxf(v.z*inv + bv.z, 0.f); v.w = fmaxf(v.w*inv + bv.w, 0.f);
            dst[j] = v;
        }
    }
}

// ----------------------------- launch 3: agg phase 1 + int8 quantize ----------
__global__ void k_agg(const int* __restrict__ neigh) {
    __shared__ float red[128];
    int u = blockIdx.x;
    int n0 = neigh[3*u], n1 = neigh[3*u+1], n2 = neigh[3*u+2];
    float inv = 1.f / (1.f + (n0 >= 0) + (n1 >= 0) + (n2 >= 0));
    const float4* s  = (const float4*)(g_h + (size_t)u*HID);
    const float4* p0 = (const float4*)(g_h + (size_t)(n0 >= 0 ? n0 : 0)*HID);
    const float4* p1 = (const float4*)(g_h + (size_t)(n1 >= 0 ? n1 : 0)*HID);
    const float4* p2 = (const float4*)(g_h + (size_t)(n2 >= 0 ? n2 : 0)*HID);
    int j = threadIdx.x;
    float4 v = s[j];
    if (n0 >= 0) { float4 t = p0[j]; v.x += t.x; v.y += t.y; v.z += t.z; v.w += t.w; }
    if (n1 >= 0) { float4 t = p1[j]; v.x += t.x; v.y += t.y; v.z += t.z; v.w += t.w; }
    if (n2 >= 0) { float4 t = p2[j]; v.x += t.x; v.y += t.y; v.z += t.z; v.w += t.w; }
    v.x *= inv; v.y *= inv; v.z *= inv; v.w *= inv;
    float mx = fmaxf(fmaxf(fabsf(v.x), fabsf(v.y)), fmaxf(fabsf(v.z), fabsf(v.w)));
    red[j] = mx; __syncthreads();
    for (int st = 64; st; st >>= 1) {
        if (j < st) red[j] = fmaxf(red[j], red[j + st]);
        __syncthreads();
    }
    float sc = fmaxf(red[0], 1e-30f) / 127.f;
    float inv_s = 1.f / sc;
    char4 c1, c2;
    quant2(v.x, sc, inv_s, (int8_t&)c1.x, (int8_t&)c2.x);
    quant2(v.y, sc, inv_s, (int8_t&)c1.y, (int8_t&)c2.y);
    quant2(v.z, sc, inv_s, (int8_t&)c1.z, (int8_t&)c2.z);
    quant2(v.w, sc, inv_s, (int8_t&)c1.w, (int8_t&)c2.w);
    *(char4*)(gAq1 + (size_t)u*1024 + 4*j) = c1;
    *(char4*)(gAq2 + (size_t)u*1024 + 4*j) = c2;
    if (j == 0) g_sA[u] = sc;
}

// ----------------------------- int8x2 GEMM (modes 0,1) ------------------------
// D = sA[m]*sB[n]*(P11 + (P12+P21)/128), block 128x64, warp 32x32
// mode 0: Cout[m*512+n] = D + bias[n]
// mode 1: gZ = split(elu(D + cvec + t*wt + r*wr))
#define I8R 48                                  // smem row bytes (32 data + 16 pad)
#define I8STAGE (2*128*I8R + 2*64*I8R)          // 18432 B
__global__ __launch_bounds__(256, 2) void k_mma8(
        int mode, int M, int K, int strideB,
        const float* __restrict__ bias,
        const float* __restrict__ wt, const float* __restrict__ wr,
        const float* __restrict__ tv, const float* __restrict__ rv,
        float* __restrict__ Cout) {
    const int8_t* Bq1 = (mode == 0) ? gB0q1 : gB1q1;
    const int8_t* Bq2 = (mode == 0) ? gB0q2 : gB1q2;
    const float*  sB  = (mode == 0) ? g_sB0 : g_sB1;

    __shared__ __align__(16) char sm8[2*I8STAGE];   // 36864 B
    const int tid  = threadIdx.x;
    const int wid  = tid >> 5;
    const int lane = tid & 31;
    const int gid  = lane >> 2;
    const int tig  = lane & 3;
    const int m0 = blockIdx.y * 128;
    const int n0 = blockIdx.x * 64;
    const int wm = (wid & 3) * 32;
    const int wn = (wid >> 2) * 32;
    const int Cn = K >> 5;

    const uint32_t sbase = (uint32_t)__cvta_generic_to_shared(sm8);
    const int am = lane >> 3;
    const int ar = lane & 7;
    const uint32_t aoff = (uint32_t)((wm + (am & 1)*8 + ar)*I8R + (am >> 1)*16);
    const uint32_t boff = (uint32_t)((wn + (am >> 1)*8 + ar)*I8R + (am & 1)*16);

    int acc1[2][4][4], acc2[2][4][4];
    #pragma unroll
    for (int i = 0; i < 2; i++)
        #pragma unroll
        for (int j = 0; j < 4; j++)
            #pragma unroll
            for (int q = 0; q < 4; q++) { acc1[i][j][q] = 0; acc2[i][j][q] = 0; }

    const int crow = tid >> 1, cseg = tid & 1;
    const int brow = (tid & 127) >> 1;
    auto copy_chunk = [&](int c, int s) {
        const size_t kb = (size_t)c*32 + cseg*16;
        uint32_t ad = sbase + (uint32_t)(s*I8STAGE + crow*I8R + cseg*16);
        cp16(ad,             gAq1 + (size_t)(m0+crow)*1024 + kb);
        cp16(ad + 128*I8R,   gAq2 + (size_t)(m0+crow)*1024 + kb);
        const int8_t* Bsrc = (tid < 128) ? Bq1 : Bq2;
        uint32_t bd = sbase + (uint32_t)(s*I8STAGE + 2*128*I8R + ((tid >= 128) ? 64*I8R : 0)
                                         + brow*I8R + cseg*16);
        cp16(bd, Bsrc + (size_t)(n0+brow)*strideB + kb);
        asm volatile("cp.async.commit_group;" ::: "memory");
    };

    copy_chunk(0, 0);
    for (int c = 0; c < Cn; c++) {
        const int s = c & 1;
        asm volatile("cp.async.wait_group 0;" ::: "memory");
        __syncthreads();
        if (c + 1 < Cn) copy_chunk(c + 1, s ^ 1);

        const uint32_t sb = sbase + (uint32_t)(s*I8STAGE);
        uint32_t a1[2][4], a2[2][4], b1[2][4], b2[2][4];
        #pragma unroll
        for (int i = 0; i < 2; i++) {
            uint32_t adr = sb + aoff + i*16*I8R;
            ldm_x4(a1[i], adr);
            ldm_x4(a2[i], adr + 128*I8R);
        }
        #pragma unroll
        for (int jp = 0; jp < 2; jp++) {
            uint32_t adr = sb + (uint32_t)(2*128*I8R) + boff + jp*16*I8R;
            ldm_x4(b1[jp], adr);
            ldm_x4(b2[jp], adr + 64*I8R);
        }
        #pragma unroll
        for (int i = 0; i < 2; i++)
            #pragma unroll
            for (int j = 0; j < 4; j++)
                mma_s8(acc1[i][j], a1[i], b1[j>>1][(j&1)*2], b1[j>>1][(j&1)*2+1]);
        #pragma unroll
        for (int i = 0; i < 2; i++)
            #pragma unroll
            for (int j = 0; j < 4; j++)
                mma_s8(acc2[i][j], a1[i], b2[j>>1][(j&1)*2], b2[j>>1][(j&1)*2+1]);
        #pragma unroll
        for (int i = 0; i < 2; i++)
            #pragma unroll
            for (int j = 0; j < 4; j++)
                mma_s8(acc2[i][j], a2[i], b1[j>>1][(j&1)*2], b1[j>>1][(j&1)*2+1]);
    }

    // ----- epilogue -----
    #pragma unroll
    for (int i = 0; i < 2; i++) {
        #pragma unroll
        for (int r2 = 0; r2 < 2; r2++) {
            int m = m0 + wm + i*16 + gid + r2*8;
            if (m >= M) continue;
            float sa = g_sA[m];
            float t = 0.f, r = 0.f;
            if (mode == 1) { t = tv[m]; r = rv[m]; }
            #pragma unroll
            for (int j = 0; j < 4; j++) {
                int n = n0 + wn + j*8 + tig*2;
                float2 sbv = *(const float2*)&sB[n];
                float v0 = sa*sbv.x*((float)acc1[i][j][r2*2]   + (float)acc2[i][j][r2*2]  *0.0078125f);
                float v1 = sa*sbv.y*((float)acc1[i][j][r2*2+1] + (float)acc2[i][j][r2*2+1]*0.0078125f);
                if (mode == 0) {
                    float2 bv = *(const float2*)&bias[n];
                    *(float2*)(Cout + (size_t)m*512 + n) = make_float2(v0 + bv.x, v1 + bv.y);
                } else {
                    float2 cv = *(const float2*)&g_cvec[n];
                    float2 wtv = *(const float2*)&wt[n];
                    float2 wrv = *(const float2*)&wr[n];
                    float z0 = eluf(v0 + cv.x + t*wtv.x + r*wrv.x);
                    float z1 = eluf(v1 + cv.y + t*wtv.y + r*wrv.y);
                    __nv_bfloat16 h0, l0, h1, l1;
                    split_bf(z0, h0, l0); split_bf(z1, h1, l1);
                    ushort2 sh = { __bfloat16_as_ushort(h0), __bfloat16_as_ushort(h1) };
                    ushort2 sl = { __bfloat16_as_ushort(l0), __bfloat16_as_ushort(l1) };
                    *(ushort2*)(gZ_hi + (size_t)m*512 + n) = sh;
                    *(ushort2*)(gZ_lo + (size_t)m*512 + n) = sl;
                }
            }
        }
    }
}

// ----------------------------- bf16x3 GEMM2 + fused logits --------------------
#define SROW 40
__global__ __launch_bounds__(256, 2) void k_mma2(
        const float* __restrict__ bias, const float* __restrict__ W3,
        float* __restrict__ Cout) {
    const int M = NNODE, K = 512;
    __shared__ __align__(16) __nv_bfloat16 sm[4*128*SROW];
    const int tid  = threadIdx.x;
    const int wid  = tid >> 5;
    const int lane = tid & 31;
    const int gid  = lane >> 2;
    const int tig  = lane & 3;
    const int m0 = blockIdx.y * 128;
    const int n0 = blockIdx.x * 128;
    const int wm = (wid & 3) * 32;
    const int wn = (wid >> 2) * 64;
    const int Cn = K >> 5;

    const uint32_t sbase = (uint32_t)__cvta_generic_to_shared(sm);
    const int am = lane >> 3;
    const int ar = lane & 7;
    const int rA = wm + (am & 1)*8 + ar;
    const int cA = (am >> 1)*8;
    const int rB = wn + (am >> 1)*8 + ar;
    const int cB = (am & 1)*8;
    const uint32_t offAh = sbase;
    const uint32_t offAl = sbase + 1u*128*SROW*2;
    const uint32_t offBh = sbase + 2u*128*SROW*2;
    const uint32_t offBl = sbase + 3u*128*SROW*2;

    float acc[2][8][4];
    #pragma unroll
    for (int i = 0; i < 2; i++)
        #pragma unroll
        for (int j = 0; j < 8; j++)
            #pragma unroll
            for (int q = 0; q < 4; q++) acc[i][j][q] = 0.f;

    uint4 rAh[2], rAl[2], rBh[2], rBl[2];
    auto load_g = [&](int c) {
        const size_t kb = (size_t)c * 32;
        #pragma unroll
        for (int it = 0; it < 2; it++) {
            int idx = it*256 + tid;
            int row = idx >> 2, seg = idx & 3;
            rAh[it] = *(const uint4*)(gZ_hi + (size_t)(m0+row)*512 + kb + seg*8);
            rAl[it] = *(const uint4*)(gZ_lo + (size_t)(m0+row)*512 + kb + seg*8);
            rBh[it] = *(const uint4*)(gB2_hi + (size_t)(n0+row)*1024 + kb + seg*8);
            rBl[it] = *(const uint4*)(gB2_lo + (size_t)(n0+row)*1024 + kb + seg*8);
        }
    };
    auto store_s = [&]() {
        #pragma unroll
        for (int it = 0; it < 2; it++) {
            int idx = it*256 + tid;
            int row = idx >> 2, seg = idx & 3;
            int so = row*SROW + seg*8;
            *(uint4*)(sm + 0*128*SROW + so) = rAh[it];
            *(uint4*)(sm + 1*128*SROW + so) = rAl[it];
            *(uint4*)(sm + 2*128*SROW + so) = rBh[it];
            *(uint4*)(sm + 3*128*SROW + so) = rBl[it];
        }
    };

    load_g(0);
    for (int c = 0; c < Cn; c++) {
        store_s();
        __syncthreads();
        if (c + 1 < Cn) load_g(c + 1);
        #pragma unroll
        for (int ks = 0; ks < 32; ks += 16) {
            uint32_t aH[2][4], aL[2][4];
            #pragma unroll
            for (int i = 0; i < 2; i++) {
                uint32_t adr = (uint32_t)(((rA + i*16)*SROW + ks + cA) * 2);
                ldm_x4(aH[i], offAh + adr);
                ldm_x4(aL[i], offAl + adr);
            }
            #pragma unroll
            for (int jp = 0; jp < 4; jp++) {
                uint32_t bh[4], bl[4];
                uint32_t adr = (uint32_t)(((rB + jp*16)*SROW + ks + cB) * 2);
                ldm_x4(bh, offBh + adr);
                ldm_x4(bl, offBl + adr);
                #pragma unroll
                for (int i = 0; i < 2; i++) {
                    mma_bf16(acc[i][2*jp],   aH[i], bh[0], bh[1]);
                    mma_bf16(acc[i][2*jp],   aH[i], bl[0], bl[1]);
                    mma_bf16(acc[i][2*jp],   aL[i], bh[0], bh[1]);
                    mma_bf16(acc[i][2*jp+1], aH[i], bh[2], bh[3]);
                    mma_bf16(acc[i][2*jp+1], aH[i], bl[2], bl[3]);
                    mma_bf16(acc[i][2*jp+1], aL[i], bh[2], bh[3]);
                }
            }
        }
        __syncthreads();
    }

    #pragma unroll
    for (int i = 0; i < 2; i++) {
        #pragma unroll
        for (int r2 = 0; r2 < 2; r2++) {
            int m = m0 + wm + i*16 + gid + r2*8;
            if (m >= M) continue;
            float part = 0.f;
            #pragma unroll
            for (int j = 0; j < 8; j++) {
                int n = n0 + wn + j*8 + tig*2;
                float2 bv = *(const float2*)&bias[n];
                float2 w3 = *(const float2*)&W3[n];
                part += eluf(acc[i][j][r2*2] + bv.x)*w3.x
                      + eluf(acc[i][j][r2*2+1] + bv.y)*w3.y;
            }
            part += __shfl_xor_sync(0xffffffffu, part, 1);
            part += __shfl_xor_sync(0xffffffffu, part, 2);
            if (tig == 0) atomicAdd(&Cout[m], part);
        }
    }
}

// ----------------------------- launch 5: hf + cvec ----------------------------
__global__ void k_hfcvec(const float* __restrict__ out, const float* __restrict__ W1h,
                         const float* __restrict__ bh1) {
    __shared__ float red[256];
    const float* hf = out + (size_t)OFF_EMB + (size_t)NNODE*HID;
    int n = blockIdx.x;
    int t = threadIdx.x;
    if (n == 0) {
        if (t < 256) { g_hf[t] = hf[t]; g_hf[t + 256] = hf[t + 256]; }
    }
    float s = 0.f;
    for (int k = t; k < HID; k += 256)
        s += hf[k] * W1h[(size_t)k*512 + n];
    red[t] = s;
    __syncthreads();
    for (int st = 128; st; st >>= 1) {
        if (t < st) red[t] += red[t + st];
        __syncthreads();
    }
    if (t == 0) g_cvec[n] = red[0] + bh1[n];
}

// ----------------------------- launch 6: build Bm + quantize -> gB1 -----------
__global__ void k_buildsplit(const float* __restrict__ W1h) {
    __shared__ float red[256];
    int n = blockIdx.x;
    int tid = threadIdx.x;
    float v[4];
    float mx = 0.f;
    #pragma unroll
    for (int it = 0; it < 4; it++) {
        int k = tid + 256*it;
        float x = W1h[(size_t)(512 + k)*512 + n];
        if (k < 512) x += g_hf[k] * W1h[(size_t)(1536 + k)*512 + n];
        v[it] = x;
        mx = fmaxf(mx, fabsf(x));
    }
    red[tid] = mx; __syncthreads();
    for (int st = 128; st; st >>= 1) {
        if (tid < st) red[tid] = fmaxf(red[tid], red[tid + st]);
        __syncthreads();
    }
    float s = fmaxf(red[0], 1e-30f) / 127.f;
    float inv_s = 1.f / s;
    #pragma unroll
    for (int it = 0; it < 4; it++) {
        int k = tid + 256*it;
        int8_t q1, q2; quant2(v[it], s, inv_s, q1, q2);
        gB1q1[(size_t)n*1024 + k] = q1;
        gB1q2[(size_t)n*1024 + k] = q2;
    }
    if (tid == 0) g_sB1[n] = s;
}

// ----------------------------- launch 7: ef + int8 quantize -------------------
__global__ void k_xef(float* __restrict__ out, const int* __restrict__ bch,
                      const float* __restrict__ tval, const float* __restrict__ isroot) {
    __shared__ float red[256];
    int u = blockIdx.x;
    int tid = threadIdx.x;
    int bc = bch[u];
    const float* ht = out + (size_t)OFF_EMB + (size_t)bc*512;
    float* ef = out + (size_t)OFF_EF + (size_t)u*2050;
    float hv[2], abv[2];
    float mx = 0.f;
    #pragma unroll
    for (int it = 0; it < 2; it++) {
        int j = tid + 256*it;
        float h = ht[j], f = g_hf[j];
        float ab = fabsf(f - h);
        hv[it] = h; abv[it] = ab;
        ef[j] = f; ef[512 + j] = h; ef[1024 + j] = ab; ef[1536 + j] = f*h;
        mx = fmaxf(mx, fmaxf(fabsf(h), ab));
    }
    red[tid] = mx; __syncthreads();
    for (int st = 128; st; st >>= 1) {
        if (tid < st) red[tid] = fmaxf(red[tid], red[tid + st]);
        __syncthreads();
    }
    float s = fmaxf(red[0], 1e-30f) / 127.f;
    float inv_s = 1.f / s;
    #pragma unroll
    for (int it = 0; it < 2; it++) {
        int j = tid + 256*it;
        int8_t q1, q2;
        quant2(hv[it], s, inv_s, q1, q2);
        gAq1[(size_t)u*1024 + j] = q1;
        gAq2[(size_t)u*1024 + j] = q2;
        quant2(abv[it], s, inv_s, q1, q2);
        gAq1[(size_t)u*1024 + 512 + j] = q1;
        gAq2[(size_t)u*1024 + 512 + j] = q2;
    }
    if (tid == 0) {
        ef[2048] = tval[u]; ef[2049] = isroot[u];
        g_sA[u] = s;
    }
}

// ----------------------------- softmax ---------------------------------------
__global__ void k_softmax(float* __restrict__ out) {
    __shared__ float red[1024];
    int tid = threadIdx.x;
    float m = -1e30f;
    for (int i = tid; i < NNODE; i += 1024) m = fmaxf(m, out[i]);
    red[tid] = m; __syncthreads();
    for (int s = 512; s; s >>= 1) {
        if (tid < s) red[tid] = fmaxf(red[tid], red[tid + s]);
        __syncthreads();
    }
    float M = red[0]; __syncthreads();
    float sum = 0.f;
    for (int i = tid; i < NNODE; i += 1024) sum += __expf(out[i] - M);
    red[tid] = sum; __syncthreads();
    for (int s = 512; s; s >>= 1) {
        if (tid < s) red[tid] += red[tid + s];
        __syncthreads();
    }
    float inv = 1.f / red[0];
    for (int i = tid; i < NNODE; i += 1024)
        out[NNODE + i] = __expf(out[i] - M) * inv;
}

// ----------------------------- launcher --------------------------------------
extern "C" void kernel_launch(void* const* d_in, const int* in_sizes, int n_in,
                              void* d_out, int out_size) {
    const int*   ns     = (const int*)d_in[0];
    const int*   ch0    = (const int*)d_in[1];
    const int*   ch1    = (const int*)d_in[2];
    const int*   parent = (const int*)d_in[3];
    const int*   neigh  = (const int*)d_in[4];
    const int*   bch    = (const int*)d_in[5];
    const int*   focal  = (const int*)d_in[6];
    const float* tv     = (const float*)d_in[7];
    const float* isroot = (const float*)d_in[8];
    const float* W1     = (const float*)d_in[9];
    const float* b1     = (const float*)d_in[10];
    const float* W2     = (const float*)d_in[11];
    const float* b2     = (const float*)d_in[12];
    const float* Wh1    = (const float*)d_in[13];
    const float* bh1    = (const float*)d_in[14];
    const float* Wh2    = (const float*)d_in[15];
    const float* bh2    = (const float*)d_in[16];
    const float* Wh3    = (const float*)d_in[17];
    const float* bh3    = (const float*)d_in[18];
    float* out = (float*)d_out;

    dim3 gm8(8, 64);
    dim3 gm2(4, 64);
    k_prep<<<5121, 256>>>(W2, Wh2, ns, focal, W1, bh3, out);   // 1
    k_tree<<<512, 256>>>(ch0, ch1, parent, neigh, b1);         // 2 (tree + agg0)
    k_agg<<<NROW, 128>>>(neigh);                               // 3 (agg1 + quant)
    // 4 (profiled slot): GEMM0 int8
    k_mma8<<<gm8, 256>>>(0, NROW, 512, 512, b2,
                         nullptr, nullptr, nullptr, nullptr, out + OFF_EMB);
    k_hfcvec<<<512, 256>>>(out, Wh1, bh1);                     // 5
    k_buildsplit<<<512, 256>>>(Wh1);                           // 6
    k_xef<<<NNODE, 256>>>(out, bch, tv, isroot);               // 7
    // 8: GEMM1 int8
    k_mma8<<<gm8, 256>>>(1, NNODE, 1024, 1024, nullptr,
                         Wh1 + (size_t)2048*512, Wh1 + (size_t)2049*512,
                         tv, isroot, nullptr);
    // 9: GEMM2 bf16x3 + fused logits
    k_mma2<<<gm2, 256>>>(bh2, Wh3, out);
    k_softmax<<<1, 1024>>>(out);                               // 10
}

// round 16
// speedup vs baseline: 1.3400x; 1.3400x over previous
#include <cuda_runtime.h>
#include <cuda_bf16.h>
#include <cstdint>

#define NLEAF 4096
#define NNODE 8191
#define NROW  8192
#define HID   512

#define OFF_EF     16382
#define OFF_EMB    16807932
#define OFF_FOCAL  21002236

// ----------------------------- scratch ---------------------------------------
__device__ float g_dW[NROW*HID];
__device__ float g_h[NROW*HID];
__device__ float g_cvec[HID];
__device__ float g_hf[HID];
__device__ float g_c[NNODE];
__device__ int   g_postF[NNODE];
__device__ int   g_preF[NNODE];

// bf16 split operand buffers (k-contiguous)
__device__ __nv_bfloat16 gA_hi[(size_t)NROW*1024];
__device__ __nv_bfloat16 gA_lo[(size_t)NROW*1024];
__device__ __nv_bfloat16 gZ_hi[(size_t)NROW*512];
__device__ __nv_bfloat16 gZ_lo[(size_t)NROW*512];
__device__ __nv_bfloat16 gB0_hi[(size_t)512*1024];
__device__ __nv_bfloat16 gB0_lo[(size_t)512*1024];
__device__ __nv_bfloat16 gB1_hi[(size_t)512*1024];
__device__ __nv_bfloat16 gB1_lo[(size_t)512*1024];
__device__ __nv_bfloat16 gB2_hi[(size_t)512*1024];
__device__ __nv_bfloat16 gB2_lo[(size_t)512*1024];

// ----------------------------- helpers ----------------------------------------
__device__ __forceinline__ void st_rel(int* p, int v) {
    asm volatile("st.release.gpu.global.b32 [%0], %1;" :: "l"(p), "r"(v) : "memory");
}
__device__ __forceinline__ int ld_acq(const int* p) {
    int v;
    asm volatile("ld.acquire.gpu.global.b32 %0, [%1];" : "=r"(v) : "l"(p) : "memory");
    return v;
}
__device__ __forceinline__ void split_bf(float v, __nv_bfloat16 &h, __nv_bfloat16 &l) {
    h = __float2bfloat16(v);
    l = __float2bfloat16(v - __bfloat162float(h));
}
__device__ __forceinline__ float eluf(float x) { return x > 0.f ? x : expm1f(x); }

__device__ __forceinline__ void mma_bf16(float* d, const uint32_t* a, uint32_t b0, uint32_t b1) {
    asm volatile(
        "mma.sync.aligned.m16n8k16.row.col.f32.bf16.bf16.f32 "
        "{%0,%1,%2,%3}, {%4,%5,%6,%7}, {%8,%9}, {%0,%1,%2,%3};"
        : "+f"(d[0]), "+f"(d[1]), "+f"(d[2]), "+f"(d[3])
        : "r"(a[0]), "r"(a[1]), "r"(a[2]), "r"(a[3]), "r"(b0), "r"(b1));
}
__device__ __forceinline__ void ldm_x4(uint32_t* r, uint32_t saddr) {
    asm volatile("ldmatrix.sync.aligned.m8n8.x4.shared.b16 {%0,%1,%2,%3}, [%4];"
        : "=r"(r[0]), "=r"(r[1]), "=r"(r[2]), "=r"(r[3]) : "r"(saddr));
}
__device__ __forceinline__ void cp16(uint32_t dst, const void* src) {
    asm volatile("cp.async.cg.shared.global [%0], [%1], 16;" :: "r"(dst), "l"(src));
}

// ----------------------------- launch 1: prep ---------------------------------
__global__ void k_prep(const float* __restrict__ W2, const float* __restrict__ Wh2,
                       const int* __restrict__ ns, const int* __restrict__ focal,
                       const float* __restrict__ W1, const float* __restrict__ bh3,
                       float* __restrict__ out) {
    int b = blockIdx.x;
    if (b < 1024) {
        if (b < 64) {
            int i = b*256 + threadIdx.x;
            if (i < NNODE) { g_postF[i] = 0; out[i] = bh3[0]; }
            else if (i < 2*NNODE) g_preF[i - NNODE] = 0;
        }
        const float* W = (b < 512) ? W2 : Wh2;
        __nv_bfloat16* bh = (b < 512) ? gB0_hi : gB2_hi;
        __nv_bfloat16* bl = (b < 512) ? gB0_lo : gB2_lo;
        int n = b & 511;
        for (int k = threadIdx.x; k < 512; k += blockDim.x) {
            float v = W[(size_t)k*512 + n];
            __nv_bfloat16 h, l; split_bf(v, h, l);
            bh[(size_t)n*1024 + k] = h;
            bl[(size_t)n*1024 + k] = l;
        }
        return;
    }
    int bb = b - 1024;
    int u, src;
    if (bb == NLEAF) { u = NNODE; src = focal[0]; }
    else {
        u = bb; src = ns[bb];
        if (threadIdx.x == 0) out[OFF_FOCAL + bb] = (bb == focal[0]) ? 1.f : 0.f;
        if (src < 0) return;
    }
    if (threadIdx.x < 128) {
        const float4* w = (const float4*)(W1 + (size_t)src*HID);
        float4* d = (float4*)(g_dW + (size_t)u*HID);
        d[threadIdx.x] = w[threadIdx.x];
    }
}

// ----------------------------- launch 2: tree + agg phase 0 -------------------
__global__ void k_tree(const int* __restrict__ ch0, const int* __restrict__ ch1,
                       const int* __restrict__ parent, const int* __restrict__ neigh,
                       const float* __restrict__ bias) {
    const int w    = blockIdx.x * (blockDim.x >> 5) + (threadIdx.x >> 5);
    const int lane = threadIdx.x & 31;
    const int NI   = NNODE - NLEAF;
    const int root = NNODE - 1;

    if (w < NI) {
        const int u = NLEAF + w;
        const int a = ch0[u], b = ch1[u];

        if (a >= NLEAF) while (!ld_acq(&g_postF[a])) { }
        if (b >= NLEAF) while (!ld_acq(&g_postF[b])) { }
        __syncwarp();
        float ca = __ldcg(&g_c[a]);
        float cb = __ldcg(&g_c[b]);
        float cu = 1.f / (3.f - ca - cb);
        const float4* pa = (const float4*)(g_dW + (size_t)a*HID);
        const float4* pb = (const float4*)(g_dW + (size_t)b*HID);
        float4*       pu = (float4*)(g_dW + (size_t)u*HID);
        #pragma unroll
        for (int j = 0; j < 4; j++) {
            int c4 = lane + j*32;
            float4 x = __ldcg(pa + c4), y = __ldcg(pb + c4), r;
            r.x = cu*(x.x+y.x); r.y = cu*(x.y+y.y);
            r.z = cu*(x.z+y.z); r.w = cu*(x.w+y.w);
            pu[c4] = r;
        }
        if (lane == 0) g_c[u] = cu;
        __threadfence();
        __syncwarp();
        if (lane == 0) {
            st_rel(&g_postF[u], 1);
            if (u == root) st_rel(&g_preF[u], 1);
        }
        __syncwarp();

        if (u != root) {
            const int p = parent[u];
            while (!ld_acq(&g_preF[p])) { }
            __syncwarp();
            const float4* pp = (const float4*)(g_dW + (size_t)p*HID);
            #pragma unroll
            for (int j = 0; j < 4; j++) {
                int c4 = lane + j*32;
                float4 x = __ldcg(pp + c4);
                float4 r = pu[c4];
                r.x += cu*x.x; r.y += cu*x.y; r.z += cu*x.z; r.w += cu*x.w;
                pu[c4] = r;
            }
            __threadfence();
            __syncwarp();
            if (lane == 0) st_rel(&g_preF[u], 1);
            __syncwarp();
        }
    }

    // ---- agg phase 0: rows 2w, 2w+1 ----
    #pragma unroll
    for (int q = 0; q < 2; q++) {
        int rrow = 2*w + q;
        int n0 = neigh[3*rrow], n1 = neigh[3*rrow+1], n2 = neigh[3*rrow+2];
        if (lane == 0) {
            if (rrow >= NLEAF && rrow < NNODE) while (!ld_acq(&g_preF[rrow])) { }
            if (n0 >= NLEAF && n0 < NNODE)     while (!ld_acq(&g_preF[n0])) { }
            if (n1 >= NLEAF && n1 < NNODE)     while (!ld_acq(&g_preF[n1])) { }
            if (n2 >= NLEAF && n2 < NNODE)     while (!ld_acq(&g_preF[n2])) { }
        }
        __syncwarp();
        float inv = 1.f / (1.f + (n0 >= 0) + (n1 >= 0) + (n2 >= 0));
        const float4* s  = (const float4*)(g_dW + (size_t)rrow*HID);
        const float4* p0 = (const float4*)(g_dW + (size_t)(n0 >= 0 ? n0 : 0)*HID);
        const float4* p1 = (const float4*)(g_dW + (size_t)(n1 >= 0 ? n1 : 0)*HID);
        const float4* p2 = (const float4*)(g_dW + (size_t)(n2 >= 0 ? n2 : 0)*HID);
        float4* dst = (float4*)(g_h + (size_t)rrow*HID);
        const float4* bb4 = (const float4*)bias;
        #pragma unroll
        for (int j4 = 0; j4 < 4; j4++) {
            int j = lane + j4*32;
            float4 v = __ldcg(s + j);
            if (n0 >= 0) { float4 t = __ldcg(p0 + j); v.x += t.x; v.y += t.y; v.z += t.z; v.w += t.w; }
            if (n1 >= 0) { float4 t = __ldcg(p1 + j); v.x += t.x; v.y += t.y; v.z += t.z; v.w += t.w; }
            if (n2 >= 0) { float4 t = __ldcg(p2 + j); v.x += t.x; v.y += t.y; v.z += t.z; v.w += t.w; }
            float4 bv = bb4[j];
            v.x = fmaxf(v.x*inv + bv.x, 0.f); v.y = fmaxf(v.y*inv + bv.y, 0.f);
            v.z = fmaxf(v.z*inv + bv.z, 0.f); v.w = fmaxf(v.w*inv + bv.w, 0.f);
            dst[j] = v;
        }
    }
}

// ----------------------------- launch 3: agg phase 1 + split ------------------
__global__ void k_agg(const int* __restrict__ neigh) {
    int u = blockIdx.x;
    int n0 = neigh[3*u], n1 = neigh[3*u+1], n2 = neigh[3*u+2];
    float inv = 1.f / (1.f + (n0 >= 0) + (n1 >= 0) + (n2 >= 0));
    const float4* s  = (const float4*)(g_h + (size_t)u*HID);
    const float4* p0 = (const float4*)(g_h + (size_t)(n0 >= 0 ? n0 : 0)*HID);
    const float4* p1 = (const float4*)(g_h + (size_t)(n1 >= 0 ? n1 : 0)*HID);
    const float4* p2 = (const float4*)(g_h + (size_t)(n2 >= 0 ? n2 : 0)*HID);
    int j = threadIdx.x;
    float4 v = s[j];
    if (n0 >= 0) { float4 t = p0[j]; v.x += t.x; v.y += t.y; v.z += t.z; v.w += t.w; }
    if (n1 >= 0) { float4 t = p1[j]; v.x += t.x; v.y += t.y; v.z += t.z; v.w += t.w; }
    if (n2 >= 0) { float4 t = p2[j]; v.x += t.x; v.y += t.y; v.z += t.z; v.w += t.w; }
    v.x *= inv; v.y *= inv; v.z *= inv; v.w *= inv;
    __nv_bfloat16 h0,l0,h1,l1,h2,l2,h3,l3;
    split_bf(v.x, h0, l0); split_bf(v.y, h1, l1);
    split_bf(v.z, h2, l2); split_bf(v.w, h3, l3);
    ushort4 sh = { __bfloat16_as_ushort(h0), __bfloat16_as_ushort(h1),
                   __bfloat16_as_ushort(h2), __bfloat16_as_ushort(h3) };
    ushort4 sl = { __bfloat16_as_ushort(l0), __bfloat16_as_ushort(l1),
                   __bfloat16_as_ushort(l2), __bfloat16_as_ushort(l3) };
    *(ushort4*)(gA_hi + (size_t)u*1024 + 4*j) = sh;
    *(ushort4*)(gA_lo + (size_t)u*1024 + 4*j) = sl;
}

// ----------------------------- mma.sync bf16x3 GEMM (128x64, 3 CTA/SM) --------
// mode 0: A=gA (stride 1024), B=gB0, K=512 ; Cout = D + bias (fp32)
// mode 1: A=gA (stride 1024), B=gB1, K=1024; gZ = split(elu(D + cvec + t*wt + r*wr))
// mode 2: A=gZ (stride 512),  B=gB2, K=512 ; z=elu(D+bias); atomicAdd(out[m], z*W3[n])
#define SROW2 24                                   // 48 B/row: cp.async aligned, ldm conflict-free
#define ASZ   (128*SROW2)                          // A region (bf16)
#define BSZ   (64*SROW2)
#define STG   (2*ASZ + 2*BSZ)                      // 18432 B per stage
__global__ __launch_bounds__(256, 3) void k_mma(
        int mode, int M, int K,
        const float* __restrict__ bias,
        const float* __restrict__ wt, const float* __restrict__ wr,
        const float* __restrict__ tv, const float* __restrict__ rv,
        float* __restrict__ Cout) {
    const __nv_bfloat16* Ahi = (mode == 2) ? gZ_hi : gA_hi;
    const __nv_bfloat16* Alo = (mode == 2) ? gZ_lo : gA_lo;
    const __nv_bfloat16* Bhi = (mode == 0) ? gB0_hi : (mode == 1 ? gB1_hi : gB2_hi);
    const __nv_bfloat16* Blo = (mode == 0) ? gB0_lo : (mode == 1 ? gB1_lo : gB2_lo);
    const int strideA = (mode == 2) ? 512 : 1024;

    __shared__ __align__(16) __nv_bfloat16 sm[2*STG];   // 36864 B double buffered
    const int tid  = threadIdx.x;
    const int wid  = tid >> 5;
    const int lane = tid & 31;
    const int gid  = lane >> 2;
    const int tig  = lane & 3;
    const int m0 = blockIdx.y * 128;
    const int n0 = blockIdx.x * 64;
    const int wm = (wid & 3) * 32;
    const int wn = (wid >> 2) * 32;
    const int Cn = K >> 4;            // 16-wide K chunks

    const uint32_t sbase = (uint32_t)__cvta_generic_to_shared(sm);
    const int am = lane >> 3;
    const int ar = lane & 7;
    const uint32_t aoff = (uint32_t)(((wm + (am & 1)*8 + ar)*SROW2 + (am >> 1)*8) * 2);
    const uint32_t boff = (uint32_t)(((wn + (am >> 1)*8 + ar)*SROW2 + (am & 1)*8) * 2);

    float acc[2][4][4];
    #pragma unroll
    for (int i = 0; i < 2; i++)
        #pragma unroll
        for (int j = 0; j < 4; j++)
            #pragma unroll
            for (int q = 0; q < 4; q++) acc[i][j][q] = 0.f;

    // cp.async mapping: A: thread -> (row=tid>>1, seg=tid&1) for hi AND lo;
    // B: threads 0..127 -> Bhi, 128..255 -> Blo, row=(tid&127)>>1, seg=tid&1
    const int arow = tid >> 1, aseg = tid & 1;
    const int brow = (tid & 127) >> 1;
    auto copy_chunk = [&](int c, int s) {
        const size_t kb = (size_t)c*16 + aseg*8;
        uint32_t ad = sbase + (uint32_t)(s*STG + arow*SROW2 + aseg*8)*2;
        cp16(ad,         Ahi + (size_t)(m0+arow)*strideA + kb);
        cp16(ad + ASZ*2, Alo + (size_t)(m0+arow)*strideA + kb);
        const __nv_bfloat16* Bsrc = (tid < 128) ? Bhi : Blo;
        uint32_t bd = sbase + (uint32_t)(s*STG + 2*ASZ + ((tid >= 128) ? BSZ : 0)
                                         + brow*SROW2 + aseg*8)*2;
        cp16(bd, Bsrc + (size_t)(n0+brow)*1024 + kb);
        asm volatile("cp.async.commit_group;" ::: "memory");
    };

    copy_chunk(0, 0);
    for (int c = 0; c < Cn; c++) {
        const int s = c & 1;
        asm volatile("cp.async.wait_group 0;" ::: "memory");
        __syncthreads();
        if (c + 1 < Cn) copy_chunk(c + 1, s ^ 1);

        const uint32_t sb = sbase + (uint32_t)(s*STG)*2;
        uint32_t aH[2][4], aL[2][4], bh[2][4], bl[2][4];
        #pragma unroll
        for (int i = 0; i < 2; i++) {
            uint32_t adr = sb + aoff + (uint32_t)(i*16*SROW2*2);
            ldm_x4(aH[i], adr);
            ldm_x4(aL[i], adr + ASZ*2);
        }
        #pragma unroll
        for (int jp = 0; jp < 2; jp++) {
            uint32_t adr = sb + (uint32_t)(2*ASZ*2) + boff + (uint32_t)(jp*16*SROW2*2);
            ldm_x4(bh[jp], adr);
            ldm_x4(bl[jp], adr + BSZ*2);
        }
        // term-major: 8 independent accs between same-acc MMAs
        #pragma unroll
        for (int i = 0; i < 2; i++)
            #pragma unroll
            for (int j = 0; j < 4; j++)
                mma_bf16(acc[i][j], aH[i], bh[j>>1][(j&1)*2], bh[j>>1][(j&1)*2+1]);
        #pragma unroll
        for (int i = 0; i < 2; i++)
            #pragma unroll
            for (int j = 0; j < 4; j++)
                mma_bf16(acc[i][j], aH[i], bl[j>>1][(j&1)*2], bl[j>>1][(j&1)*2+1]);
        #pragma unroll
        for (int i = 0; i < 2; i++)
            #pragma unroll
            for (int j = 0; j < 4; j++)
                mma_bf16(acc[i][j], aL[i], bh[j>>1][(j&1)*2], bh[j>>1][(j&1)*2+1]);
    }

    // ----- epilogue -----
    #pragma unroll
    for (int i = 0; i < 2; i++) {
        #pragma unroll
        for (int r2 = 0; r2 < 2; r2++) {
            int m = m0 + wm + i*16 + gid + r2*8;
            if (m >= M) continue;
            float t = 0.f, r = 0.f;
            if (mode == 1) { t = tv[m]; r = rv[m]; }
            float part = 0.f;
            #pragma unroll
            for (int j = 0; j < 4; j++) {
                int n = n0 + wn + j*8 + tig*2;
                float v0 = acc[i][j][r2*2 + 0];
                float v1 = acc[i][j][r2*2 + 1];
                if (mode == 0) {
                    float2 bv = *(const float2*)&bias[n];
                    *(float2*)(Cout + (size_t)m*512 + n) = make_float2(v0 + bv.x, v1 + bv.y);
                } else if (mode == 1) {
                    float2 cv = *(const float2*)&g_cvec[n];
                    float2 wtv = *(const float2*)&wt[n];
                    float2 wrv = *(const float2*)&wr[n];
                    float z0 = eluf(v0 + cv.x + t*wtv.x + r*wrv.x);
                    float z1 = eluf(v1 + cv.y + t*wtv.y + r*wrv.y);
                    __nv_bfloat16 h0, l0, h1, l1;
                    split_bf(z0, h0, l0); split_bf(z1, h1, l1);
                    ushort2 sh = { __bfloat16_as_ushort(h0), __bfloat16_as_ushort(h1) };
                    ushort2 sl = { __bfloat16_as_ushort(l0), __bfloat16_as_ushort(l1) };
                    *(ushort2*)(gZ_hi + (size_t)m*512 + n) = sh;
                    *(ushort2*)(gZ_lo + (size_t)m*512 + n) = sl;
                } else {
                    float2 bv = *(const float2*)&bias[n];
                    float2 w3 = *(const float2*)&wt[n];
                    part += eluf(v0 + bv.x)*w3.x + eluf(v1 + bv.y)*w3.y;
                }
            }
            if (mode == 2) {
                part += __shfl_xor_sync(0xffffffffu, part, 1);
                part += __shfl_xor_sync(0xffffffffu, part, 2);
                if (tig == 0) atomicAdd(&Cout[m], part);
            }
        }
    }
}

// ----------------------------- launch 5: hf + cvec ----------------------------
__global__ void k_hfcvec(const float* __restrict__ out, const float* __restrict__ W1h,
                         const float* __restrict__ bh1) {
    __shared__ float red[256];
    const float* hf = out + (size_t)OFF_EMB + (size_t)NNODE*HID;
    int n = blockIdx.x;
    int t = threadIdx.x;
    if (n == 0) {
        if (t < 256) { g_hf[t] = hf[t]; g_hf[t + 256] = hf[t + 256]; }
    }
    float s = 0.f;
    for (int k = t; k < HID; k += 256)
        s += hf[k] * W1h[(size_t)k*512 + n];
    red[t] = s;
    __syncthreads();
    for (int st = 128; st; st >>= 1) {
        if (t < st) red[t] += red[t + st];
        __syncthreads();
    }
    if (t == 0) g_cvec[n] = red[0] + bh1[n];
}

// ----------------------------- launch 6: build Bm + split → gB1 ---------------
__global__ void k_buildsplit(const float* __restrict__ W1h) {
    int n = blockIdx.x;
    for (int k = threadIdx.x; k < 1024; k += blockDim.x) {
        float v = W1h[(size_t)(512 + k)*512 + n];
        if (k < 512) v += g_hf[k] * W1h[(size_t)(1536 + k)*512 + n];
        __nv_bfloat16 h, l; split_bf(v, h, l);
        gB1_hi[(size_t)n*1024 + k] = h;
        gB1_lo[(size_t)n*1024 + k] = l;
    }
}

// ----------------------------- launch 7: ef + X split -------------------------
__global__ void k_xef(float* __restrict__ out, const int* __restrict__ bch,
                      const float* __restrict__ tval, const float* __restrict__ isroot) {
    int u = blockIdx.x;
    int bc = bch[u];
    const float* ht = out + (size_t)OFF_EMB + (size_t)bc*512;
    float* ef = out + (size_t)OFF_EF + (size_t)u*2050;
    for (int j = threadIdx.x; j < 512; j += blockDim.x) {
        float h = ht[j], f = g_hf[j];
        float ab = fabsf(f - h), pr = f*h;
        ef[j] = f; ef[512 + j] = h; ef[1024 + j] = ab; ef[1536 + j] = pr;
        __nv_bfloat16 hh, hl, ah, al;
        split_bf(h, hh, hl); split_bf(ab, ah, al);
        gA_hi[(size_t)u*1024 + j]       = hh;
        gA_lo[(size_t)u*1024 + j]       = hl;
        gA_hi[(size_t)u*1024 + 512 + j] = ah;
        gA_lo[(size_t)u*1024 + 512 + j] = al;
    }
    if (threadIdx.x == 0) { ef[2048] = tval[u]; ef[2049] = isroot[u]; }
}

// ----------------------------- softmax ---------------------------------------
__global__ void k_softmax(float* __restrict__ out) {
    __shared__ float red[1024];
    int tid = threadIdx.x;
    float m = -1e30f;
    for (int i = tid; i < NNODE; i += 1024) m = fmaxf(m, out[i]);
    red[tid] = m; __syncthreads();
    for (int s = 512; s; s >>= 1) {
        if (tid < s) red[tid] = fmaxf(red[tid], red[tid + s]);
        __syncthreads();
    }
    float M = red[0]; __syncthreads();
    float sum = 0.f;
    for (int i = tid; i < NNODE; i += 1024) sum += __expf(out[i] - M);
    red[tid] = sum; __syncthreads();
    for (int s = 512; s; s >>= 1) {
        if (tid < s) red[tid] += red[tid + s];
        __syncthreads();
    }
    float inv = 1.f / red[0];
    for (int i = tid; i < NNODE; i += 1024)
        out[NNODE + i] = __expf(out[i] - M) * inv;
}

// ----------------------------- launcher --------------------------------------
extern "C" void kernel_launch(void* const* d_in, const int* in_sizes, int n_in,
                              void* d_out, int out_size) {
    const int*   ns     = (const int*)d_in[0];
    const int*   ch0    = (const int*)d_in[1];
    const int*   ch1    = (const int*)d_in[2];
    const int*   parent = (const int*)d_in[3];
    const int*   neigh  = (const int*)d_in[4];
    const int*   bch    = (const int*)d_in[5];
    const int*   focal  = (const int*)d_in[6];
    const float* tv     = (const float*)d_in[7];
    const float* isroot = (const float*)d_in[8];
    const float* W1     = (const float*)d_in[9];
    const float* b1     = (const float*)d_in[10];
    const float* W2     = (const float*)d_in[11];
    const float* b2     = (const float*)d_in[12];
    const float* Wh1    = (const float*)d_in[13];
    const float* bh1    = (const float*)d_in[14];
    const float* Wh2    = (const float*)d_in[15];
    const float* bh2    = (const float*)d_in[16];
    const float* Wh3    = (const float*)d_in[17];
    const float* bh3    = (const float*)d_in[18];
    float* out = (float*)d_out;

    dim3 gm(8, 64);       // 128x64 tiles over N=512
    k_prep<<<5121, 256>>>(W2, Wh2, ns, focal, W1, bh3, out);   // 1
    k_tree<<<512, 256>>>(ch0, ch1, parent, neigh, b1);         // 2
    k_agg<<<NROW, 128>>>(neigh);                               // 3
    // 4 (profiled slot): GEMM0
    k_mma<<<gm, 256>>>(0, NROW, 512, b2,
                       nullptr, nullptr, nullptr, nullptr, out + OFF_EMB);
    k_hfcvec<<<512, 256>>>(out, Wh1, bh1);                     // 5
    k_buildsplit<<<512, 256>>>(Wh1);                           // 6
    k_xef<<<NNODE, 256>>>(out, bch, tv, isroot);               // 7
    // 8: GEMM1
    k_mma<<<gm, 256>>>(1, NNODE, 1024, nullptr,
                       Wh1 + (size_t)2048*512, Wh1 + (size_t)2049*512,
                       tv, isroot, nullptr);
    // 9: GEMM2 + fused logits
    k_mma<<<gm, 256>>>(2, NNODE, 512, bh2,
                       Wh3, nullptr, nullptr, nullptr, out);
    k_softmax<<<1, 1024>>>(out);                               // 10
}

// round 17
// speedup vs baseline: 1.4356x; 1.0714x over previous
#include <cuda_runtime.h>
#include <cuda_bf16.h>
#include <cstdint>

#define NLEAF 4096
#define NNODE 8191
#define NROW  8192
#define HID   512

#define OFF_EF     16382
#define OFF_EMB    16807932
#define OFF_FOCAL  21002236

// ----------------------------- scratch ---------------------------------------
__device__ float g_dW[NROW*HID];
__device__ float g_h[NROW*HID];
__device__ float g_cvec[HID];
__device__ float g_hf[HID];
__device__ float g_c[NNODE];
__device__ int   g_postF[NNODE];
__device__ int   g_preF[NNODE];

// bf16 split operand buffers (k-contiguous)
__device__ __nv_bfloat16 gA_hi[(size_t)NROW*1024];
__device__ __nv_bfloat16 gA_lo[(size_t)NROW*1024];
__device__ __nv_bfloat16 gZ_hi[(size_t)NROW*512];
__device__ __nv_bfloat16 gZ_lo[(size_t)NROW*512];
__device__ __nv_bfloat16 gB0_hi[(size_t)512*1024];
__device__ __nv_bfloat16 gB0_lo[(size_t)512*1024];
__device__ __nv_bfloat16 gB1_hi[(size_t)512*1024];
__device__ __nv_bfloat16 gB1_lo[(size_t)512*1024];
__device__ __nv_bfloat16 gB2_hi[(size_t)512*1024];
__device__ __nv_bfloat16 gB2_lo[(size_t)512*1024];

// ----------------------------- helpers ----------------------------------------
__device__ __forceinline__ void st_rel(int* p, int v) {
    asm volatile("st.release.gpu.global.b32 [%0], %1;" :: "l"(p), "r"(v) : "memory");
}
__device__ __forceinline__ int ld_acq(const int* p) {
    int v;
    asm volatile("ld.acquire.gpu.global.b32 %0, [%1];" : "=r"(v) : "l"(p) : "memory");
    return v;
}
__device__ __forceinline__ void split_bf(float v, __nv_bfloat16 &h, __nv_bfloat16 &l) {
    h = __float2bfloat16(v);
    l = __float2bfloat16(v - __bfloat162float(h));
}
__device__ __forceinline__ float eluf(float x) { return x > 0.f ? x : expm1f(x); }

__device__ __forceinline__ void mma_bf16(float* d, const uint32_t* a, uint32_t b0, uint32_t b1) {
    asm volatile(
        "mma.sync.aligned.m16n8k16.row.col.f32.bf16.bf16.f32 "
        "{%0,%1,%2,%3}, {%4,%5,%6,%7}, {%8,%9}, {%0,%1,%2,%3};"
        : "+f"(d[0]), "+f"(d[1]), "+f"(d[2]), "+f"(d[3])
        : "r"(a[0]), "r"(a[1]), "r"(a[2]), "r"(a[3]), "r"(b0), "r"(b1));
}
__device__ __forceinline__ void ldm_x4(uint32_t* r, uint32_t saddr) {
    asm volatile("ldmatrix.sync.aligned.m8n8.x4.shared.b16 {%0,%1,%2,%3}, [%4];"
        : "=r"(r[0]), "=r"(r[1]), "=r"(r[2]), "=r"(r[3]) : "r"(saddr));
}

// ----------------------------- launch 1: prep ---------------------------------
__global__ void k_prep(const float* __restrict__ W2, const float* __restrict__ Wh2,
                       const int* __restrict__ ns, const int* __restrict__ focal,
                       const float* __restrict__ W1, const float* __restrict__ bh3,
                       float* __restrict__ out) {
    int b = blockIdx.x;
    if (b < 1024) {
        if (b < 64) {
            int i = b*256 + threadIdx.x;
            if (i < NNODE) { g_postF[i] = 0; out[i] = bh3[0]; }
            else if (i < 2*NNODE) g_preF[i - NNODE] = 0;
        }
        const float* W = (b < 512) ? W2 : Wh2;
        __nv_bfloat16* bh = (b < 512) ? gB0_hi : gB2_hi;
        __nv_bfloat16* bl = (b < 512) ? gB0_lo : gB2_lo;
        int n = b & 511;
        for (int k = threadIdx.x; k < 512; k += blockDim.x) {
            float v = W[(size_t)k*512 + n];
            __nv_bfloat16 h, l; split_bf(v, h, l);
            bh[(size_t)n*1024 + k] = h;
            bl[(size_t)n*1024 + k] = l;
        }
        return;
    }
    int bb = b - 1024;
    int u, src;
    if (bb == NLEAF) { u = NNODE; src = focal[0]; }
    else {
        u = bb; src = ns[bb];
        if (threadIdx.x == 0) out[OFF_FOCAL + bb] = (bb == focal[0]) ? 1.f : 0.f;
        if (src < 0) return;
    }
    if (threadIdx.x < 128) {
        const float4* w = (const float4*)(W1 + (size_t)src*HID);
        float4* d = (float4*)(g_dW + (size_t)u*HID);
        d[threadIdx.x] = w[threadIdx.x];
    }
}

// ----------------------------- launch 2: tree + agg phase 0 -------------------
__global__ void k_tree(const int* __restrict__ ch0, const int* __restrict__ ch1,
                       const int* __restrict__ parent, const int* __restrict__ neigh,
                       const float* __restrict__ bias) {
    const int w    = blockIdx.x * (blockDim.x >> 5) + (threadIdx.x >> 5);
    const int lane = threadIdx.x & 31;
    const int NI   = NNODE - NLEAF;
    const int root = NNODE - 1;

    if (w < NI) {
        const int u = NLEAF + w;
        const int a = ch0[u], b = ch1[u];

        if (a >= NLEAF) while (!ld_acq(&g_postF[a])) { }
        if (b >= NLEAF) while (!ld_acq(&g_postF[b])) { }
        __syncwarp();
        float ca = __ldcg(&g_c[a]);
        float cb = __ldcg(&g_c[b]);
        float cu = 1.f / (3.f - ca - cb);
        const float4* pa = (const float4*)(g_dW + (size_t)a*HID);
        const float4* pb = (const float4*)(g_dW + (size_t)b*HID);
        float4*       pu = (float4*)(g_dW + (size_t)u*HID);
        #pragma unroll
        for (int j = 0; j < 4; j++) {
            int c4 = lane + j*32;
            float4 x = __ldcg(pa + c4), y = __ldcg(pb + c4), r;
            r.x = cu*(x.x+y.x); r.y = cu*(x.y+y.y);
            r.z = cu*(x.z+y.z); r.w = cu*(x.w+y.w);
            pu[c4] = r;
        }
        if (lane == 0) g_c[u] = cu;
        __threadfence();
        __syncwarp();
        if (lane == 0) {
            st_rel(&g_postF[u], 1);
            if (u == root) st_rel(&g_preF[u], 1);
        }
        __syncwarp();

        if (u != root) {
            const int p = parent[u];
            while (!ld_acq(&g_preF[p])) { }
            __syncwarp();
            const float4* pp = (const float4*)(g_dW + (size_t)p*HID);
            #pragma unroll
            for (int j = 0; j < 4; j++) {
                int c4 = lane + j*32;
                float4 x = __ldcg(pp + c4);
                float4 r = pu[c4];
                r.x += cu*x.x; r.y += cu*x.y; r.z += cu*x.z; r.w += cu*x.w;
                pu[c4] = r;
            }
            __threadfence();
            __syncwarp();
            if (lane == 0) st_rel(&g_preF[u], 1);
            __syncwarp();
        }
    }

    // ---- agg phase 0: rows 2w, 2w+1 ----
    #pragma unroll
    for (int q = 0; q < 2; q++) {
        int rrow = 2*w + q;
        int n0 = neigh[3*rrow], n1 = neigh[3*rrow+1], n2 = neigh[3*rrow+2];
        if (lane == 0) {
            if (rrow >= NLEAF && rrow < NNODE) while (!ld_acq(&g_preF[rrow])) { }
            if (n0 >= NLEAF && n0 < NNODE)     while (!ld_acq(&g_preF[n0])) { }
            if (n1 >= NLEAF && n1 < NNODE)     while (!ld_acq(&g_preF[n1])) { }
            if (n2 >= NLEAF && n2 < NNODE)     while (!ld_acq(&g_preF[n2])) { }
        }
        __syncwarp();
        float inv = 1.f / (1.f + (n0 >= 0) + (n1 >= 0) + (n2 >= 0));
        const float4* s  = (const float4*)(g_dW + (size_t)rrow*HID);
        const float4* p0 = (const float4*)(g_dW + (size_t)(n0 >= 0 ? n0 : 0)*HID);
        const float4* p1 = (const float4*)(g_dW + (size_t)(n1 >= 0 ? n1 : 0)*HID);
        const float4* p2 = (const float4*)(g_dW + (size_t)(n2 >= 0 ? n2 : 0)*HID);
        float4* dst = (float4*)(g_h + (size_t)rrow*HID);
        const float4* bb4 = (const float4*)bias;
        #pragma unroll
        for (int j4 = 0; j4 < 4; j4++) {
            int j = lane + j4*32;
            float4 v = __ldcg(s + j);
            if (n0 >= 0) { float4 t = __ldcg(p0 + j); v.x += t.x; v.y += t.y; v.z += t.z; v.w += t.w; }
            if (n1 >= 0) { float4 t = __ldcg(p1 + j); v.x += t.x; v.y += t.y; v.z += t.z; v.w += t.w; }
            if (n2 >= 0) { float4 t = __ldcg(p2 + j); v.x += t.x; v.y += t.y; v.z += t.z; v.w += t.w; }
            float4 bv = bb4[j];
            v.x = fmaxf(v.x*inv + bv.x, 0.f); v.y = fmaxf(v.y*inv + bv.y, 0.f);
            v.z = fmaxf(v.z*inv + bv.z, 0.f); v.w = fmaxf(v.w*inv + bv.w, 0.f);
            dst[j] = v;
        }
    }
}

// ----------------------------- launch 3: agg phase 1 + split ------------------
__global__ void k_agg(const int* __restrict__ neigh) {
    int u = blockIdx.x;
    int n0 = neigh[3*u], n1 = neigh[3*u+1], n2 = neigh[3*u+2];
    float inv = 1.f / (1.f + (n0 >= 0) + (n1 >= 0) + (n2 >= 0));
    const float4* s  = (const float4*)(g_h + (size_t)u*HID);
    const float4* p0 = (const float4*)(g_h + (size_t)(n0 >= 0 ? n0 : 0)*HID);
    const float4* p1 = (const float4*)(g_h + (size_t)(n1 >= 0 ? n1 : 0)*HID);
    const float4* p2 = (const float4*)(g_h + (size_t)(n2 >= 0 ? n2 : 0)*HID);
    int j = threadIdx.x;
    float4 v = s[j];
    if (n0 >= 0) { float4 t = p0[j]; v.x += t.x; v.y += t.y; v.z += t.z; v.w += t.w; }
    if (n1 >= 0) { float4 t = p1[j]; v.x += t.x; v.y += t.y; v.z += t.z; v.w += t.w; }
    if (n2 >= 0) { float4 t = p2[j]; v.x += t.x; v.y += t.y; v.z += t.z; v.w += t.w; }
    v.x *= inv; v.y *= inv; v.z *= inv; v.w *= inv;
    __nv_bfloat16 h0,l0,h1,l1,h2,l2,h3,l3;
    split_bf(v.x, h0, l0); split_bf(v.y, h1, l1);
    split_bf(v.z, h2, l2); split_bf(v.w, h3, l3);
    ushort4 sh = { __bfloat16_as_ushort(h0), __bfloat16_as_ushort(h1),
                   __bfloat16_as_ushort(h2), __bfloat16_as_ushort(h3) };
    ushort4 sl = { __bfloat16_as_ushort(l0), __bfloat16_as_ushort(l1),
                   __bfloat16_as_ushort(l2), __bfloat16_as_ushort(l3) };
    *(ushort4*)(gA_hi + (size_t)u*1024 + 4*j) = sh;
    *(ushort4*)(gA_lo + (size_t)u*1024 + 4*j) = sl;
}

// ----------------------------- mma.sync bf16x3 GEMM (R13-proven) --------------
// mode 0: A=gA (stride 1024), B=gB0, K=512 ; Cout = D + bias (fp32)
// mode 1: A=gA (stride 1024), B=gB1, K=1024; gZ = split(elu(D + cvec + t*wt + r*wr))
// mode 2: A=gZ (stride 512),  B=gB2, K=512 ; z=elu(D+bias); atomicAdd(out[m], z*W3[n])
#define SROW 40
__global__ __launch_bounds__(256, 2) void k_mma(
        int mode, int M, int K,
        const float* __restrict__ bias,
        const float* __restrict__ wt, const float* __restrict__ wr,
        const float* __restrict__ tv, const float* __restrict__ rv,
        float* __restrict__ Cout) {
    const __nv_bfloat16* Ahi = (mode == 2) ? gZ_hi : gA_hi;
    const __nv_bfloat16* Alo = (mode == 2) ? gZ_lo : gA_lo;
    const __nv_bfloat16* Bhi = (mode == 0) ? gB0_hi : (mode == 1 ? gB1_hi : gB2_hi);
    const __nv_bfloat16* Blo = (mode == 0) ? gB0_lo : (mode == 1 ? gB1_lo : gB2_lo);
    const int strideA = (mode == 2) ? 512 : 1024;

    __shared__ __align__(16) __nv_bfloat16 sm[4*128*SROW];
    const int tid  = threadIdx.x;
    const int wid  = tid >> 5;
    const int lane = tid & 31;
    const int gid  = lane >> 2;
    const int tig  = lane & 3;
    const int m0 = blockIdx.y * 128;
    const int n0 = blockIdx.x * 128;
    const int wm = (wid & 3) * 32;
    const int wn = (wid >> 2) * 64;
    const int Cn = K >> 5;

    const uint32_t sbase = (uint32_t)__cvta_generic_to_shared(sm);
    const int am  = lane >> 3;
    const int ar  = lane & 7;
    const int rA  = wm + (am & 1)*8 + ar;
    const int cA  = (am >> 1)*8;
    const int rB  = wn + (am >> 1)*8 + ar;
    const int cB  = (am & 1)*8;
    const uint32_t offAh = sbase;
    const uint32_t offAl = sbase + 1u*128*SROW*2;
    const uint32_t offBh = sbase + 2u*128*SROW*2;
    const uint32_t offBl = sbase + 3u*128*SROW*2;

    float acc[2][8][4];
    #pragma unroll
    for (int i = 0; i < 2; i++)
        #pragma unroll
        for (int j = 0; j < 8; j++)
            #pragma unroll
            for (int q = 0; q < 4; q++) acc[i][j][q] = 0.f;

    uint4 rAh[2], rAl[2], rBh[2], rBl[2];
    auto load_g = [&](int c) {
        const size_t kb = (size_t)c * 32;
        #pragma unroll
        for (int it = 0; it < 2; it++) {
            int idx = it*256 + tid;
            int row = idx >> 2, seg = idx & 3;
            rAh[it] = *(const uint4*)(Ahi + (size_t)(m0+row)*strideA + kb + seg*8);
            rAl[it] = *(const uint4*)(Alo + (size_t)(m0+row)*strideA + kb + seg*8);
            rBh[it] = *(const uint4*)(Bhi + (size_t)(n0+row)*1024 + kb + seg*8);
            rBl[it] = *(const uint4*)(Blo + (size_t)(n0+row)*1024 + kb + seg*8);
        }
    };
    auto store_s = [&]() {
        #pragma unroll
        for (int it = 0; it < 2; it++) {
            int idx = it*256 + tid;
            int row = idx >> 2, seg = idx & 3;
            int so = row*SROW + seg*8;
            *(uint4*)(sm + 0*128*SROW + so) = rAh[it];
            *(uint4*)(sm + 1*128*SROW + so) = rAl[it];
            *(uint4*)(sm + 2*128*SROW + so) = rBh[it];
            *(uint4*)(sm + 3*128*SROW + so) = rBl[it];
        }
    };

    load_g(0);
    for (int c = 0; c < Cn; c++) {
        store_s();
        __syncthreads();
        if (c + 1 < Cn) load_g(c + 1);
        #pragma unroll
        for (int ks = 0; ks < 32; ks += 16) {
            uint32_t aH[2][4], aL[2][4];
            #pragma unroll
            for (int i = 0; i < 2; i++) {
                uint32_t adr = (uint32_t)(((rA + i*16)*SROW + ks + cA) * 2);
                ldm_x4(aH[i], offAh + adr);
                ldm_x4(aL[i], offAl + adr);
            }
            #pragma unroll
            for (int jp = 0; jp < 4; jp++) {
                uint32_t bh[4], bl[4];
                uint32_t adr = (uint32_t)(((rB + jp*16)*SROW + ks + cB) * 2);
                ldm_x4(bh, offBh + adr);
                ldm_x4(bl, offBl + adr);
                #pragma unroll
                for (int i = 0; i < 2; i++) {
                    mma_bf16(acc[i][2*jp],   aH[i], bh[0], bh[1]);
                    mma_bf16(acc[i][2*jp],   aH[i], bl[0], bl[1]);
                    mma_bf16(acc[i][2*jp],   aL[i], bh[0], bh[1]);
                    mma_bf16(acc[i][2*jp+1], aH[i], bh[2], bh[3]);
                    mma_bf16(acc[i][2*jp+1], aH[i], bl[2], bl[3]);
                    mma_bf16(acc[i][2*jp+1], aL[i], bh[2], bh[3]);
                }
            }
        }
        __syncthreads();
    }

    // ----- epilogue -----
    #pragma unroll
    for (int i = 0; i < 2; i++) {
        #pragma unroll
        for (int r2 = 0; r2 < 2; r2++) {
            int m = m0 + wm + i*16 + gid + r2*8;
            if (m >= M) continue;
            float t = 0.f, r = 0.f;
            if (mode == 1) { t = tv[m]; r = rv[m]; }
            float part = 0.f;
            #pragma unroll
            for (int j = 0; j < 8; j++) {
                int n = n0 + wn + j*8 + tig*2;
                float v0 = acc[i][j][r2*2 + 0];
                float v1 = acc[i][j][r2*2 + 1];
                if (mode == 0) {
                    float2 bv = *(const float2*)&bias[n];
                    *(float2*)(Cout + (size_t)m*512 + n) = make_float2(v0 + bv.x, v1 + bv.y);
                } else if (mode == 1) {
                    float2 cv = *(const float2*)&g_cvec[n];
                    float2 wtv = *(const float2*)&wt[n];
                    float2 wrv = *(const float2*)&wr[n];
                    float z0 = eluf(v0 + cv.x + t*wtv.x + r*wrv.x);
                    float z1 = eluf(v1 + cv.y + t*wtv.y + r*wrv.y);
                    __nv_bfloat16 h0, l0, h1, l1;
                    split_bf(z0, h0, l0); split_bf(z1, h1, l1);
                    ushort2 sh = { __bfloat16_as_ushort(h0), __bfloat16_as_ushort(h1) };
                    ushort2 sl = { __bfloat16_as_ushort(l0), __bfloat16_as_ushort(l1) };
                    *(ushort2*)(gZ_hi + (size_t)m*512 + n) = sh;
                    *(ushort2*)(gZ_lo + (size_t)m*512 + n) = sl;
                } else {
                    float2 bv = *(const float2*)&bias[n];
                    float2 w3 = *(const float2*)&wt[n];
                    part += eluf(v0 + bv.x)*w3.x + eluf(v1 + bv.y)*w3.y;
                }
            }
            if (mode == 2) {
                part += __shfl_xor_sync(0xffffffffu, part, 1);
                part += __shfl_xor_sync(0xffffffffu, part, 2);
                if (tig == 0) atomicAdd(&Cout[m], part);
            }
        }
    }
}

// ----------------------------- launch 5: hf + cvec + Bm split (fused) ---------
// block n: cvec[n] = bh1[n] + sum_k hf[k]*W1h[k*512+n]  AND  gB1 column n.
// hf read directly from out (GEMM0 result); block 0 publishes g_hf for k_xef.
__global__ void k_hfbuild(const float* __restrict__ out, const float* __restrict__ W1h,
                          const float* __restrict__ bh1) {
    __shared__ float sh[HID];
    __shared__ float red[256];
    const float* hf = out + (size_t)OFF_EMB + (size_t)NNODE*HID;
    int n = blockIdx.x;
    int t = threadIdx.x;
    sh[t] = hf[t]; sh[t + 256] = hf[t + 256];
    if (n == 0) { g_hf[t] = sh[t]; g_hf[t + 256] = sh[t + 256]; }
    __syncthreads();
    // cvec
    float s = 0.f;
    #pragma unroll 2
    for (int k = t; k < HID; k += 256)
        s += sh[k] * W1h[(size_t)k*512 + n];
    red[t] = s;
    __syncthreads();
    for (int st = 128; st; st >>= 1) {
        if (t < st) red[t] += red[t + st];
        __syncthreads();
    }
    if (t == 0) g_cvec[n] = red[0] + bh1[n];
    // Bm build + split: k in [0,1024)
    #pragma unroll
    for (int it = 0; it < 4; it++) {
        int k = t + 256*it;
        float v = W1h[(size_t)(512 + k)*512 + n];
        if (k < 512) v += sh[k] * W1h[(size_t)(1536 + k)*512 + n];
        __nv_bfloat16 h, l; split_bf(v, h, l);
        gB1_hi[(size_t)n*1024 + k] = h;
        gB1_lo[(size_t)n*1024 + k] = l;
    }
}

// ----------------------------- launch 6: ef + X split -------------------------
__global__ void k_xef(float* __restrict__ out, const int* __restrict__ bch,
                      const float* __restrict__ tval, const float* __restrict__ isroot) {
    int u = blockIdx.x;
    int bc = bch[u];
    const float* ht = out + (size_t)OFF_EMB + (size_t)bc*512;
    float* ef = out + (size_t)OFF_EF + (size_t)u*2050;
    for (int j = threadIdx.x; j < 512; j += blockDim.x) {
        float h = ht[j], f = g_hf[j];
        float ab = fabsf(f - h), pr = f*h;
        ef[j] = f; ef[512 + j] = h; ef[1024 + j] = ab; ef[1536 + j] = pr;
        __nv_bfloat16 hh, hl, ah, al;
        split_bf(h, hh, hl); split_bf(ab, ah, al);
        gA_hi[(size_t)u*1024 + j]       = hh;
        gA_lo[(size_t)u*1024 + j]       = hl;
        gA_hi[(size_t)u*1024 + 512 + j] = ah;
        gA_lo[(size_t)u*1024 + 512 + j] = al;
    }
    if (threadIdx.x == 0) { ef[2048] = tval[u]; ef[2049] = isroot[u]; }
}

// ----------------------------- softmax (smem-cached) ---------------------------
__global__ void k_softmax(float* __restrict__ out) {
    __shared__ float red[1024];
    __shared__ float cache[NNODE];
    int tid = threadIdx.x;
    float m = -1e30f;
    for (int i = tid; i < NNODE; i += 1024) {
        float v = out[i];
        cache[i] = v;
        m = fmaxf(m, v);
    }
    red[tid] = m; __syncthreads();
    for (int s = 512; s; s >>= 1) {
        if (tid < s) red[tid] = fmaxf(red[tid], red[tid + s]);
        __syncthreads();
    }
    float M = red[0]; __syncthreads();
    float sum = 0.f;
    for (int i = tid; i < NNODE; i += 1024) {
        float e = __expf(cache[i] - M);
        cache[i] = e;
        sum += e;
    }
    red[tid] = sum; __syncthreads();
    for (int s = 512; s; s >>= 1) {
        if (tid < s) red[tid] += red[tid + s];
        __syncthreads();
    }
    float inv = 1.f / red[0];
    for (int i = tid; i < NNODE; i += 1024)
        out[NNODE + i] = cache[i] * inv;
}

// ----------------------------- launcher --------------------------------------
extern "C" void kernel_launch(void* const* d_in, const int* in_sizes, int n_in,
                              void* d_out, int out_size) {
    const int*   ns     = (const int*)d_in[0];
    const int*   ch0    = (const int*)d_in[1];
    const int*   ch1    = (const int*)d_in[2];
    const int*   parent = (const int*)d_in[3];
    const int*   neigh  = (const int*)d_in[4];
    const int*   bch    = (const int*)d_in[5];
    const int*   focal  = (const int*)d_in[6];
    const float* tv     = (const float*)d_in[7];
    const float* isroot = (const float*)d_in[8];
    const float* W1     = (const float*)d_in[9];
    const float* b1     = (const float*)d_in[10];
    const float* W2     = (const float*)d_in[11];
    const float* b2     = (const float*)d_in[12];
    const float* Wh1    = (const float*)d_in[13];
    const float* bh1    = (const float*)d_in[14];
    const float* Wh2    = (const float*)d_in[15];
    const float* bh2    = (const float*)d_in[16];
    const float* Wh3    = (const float*)d_in[17];
    const float* bh3    = (const float*)d_in[18];
    float* out = (float*)d_out;

    dim3 gm(4, 64);
    k_prep<<<5121, 256>>>(W2, Wh2, ns, focal, W1, bh3, out);   // 1
    k_tree<<<512, 256>>>(ch0, ch1, parent, neigh, b1);         // 2
    k_agg<<<NROW, 128>>>(neigh);                               // 3
    // 4: GEMM0
    k_mma<<<gm, 256>>>(0, NROW, 512, b2,
                       nullptr, nullptr, nullptr, nullptr, out + OFF_EMB);
    k_hfbuild<<<512, 256>>>(out, Wh1, bh1);                    // 5 (fused)
    k_xef<<<NNODE, 256>>>(out, bch, tv, isroot);               // 6
    // 7: GEMM1
    k_mma<<<gm, 256>>>(1, NNODE, 1024, nullptr,
                       Wh1 + (size_t)2048*512, Wh1 + (size_t)2049*512,
                       tv, isroot, nullptr);
    // 8: GEMM2 + fused logits
    k_mma<<<gm, 256>>>(2, NNODE, 512, bh2,
                       Wh3, nullptr, nullptr, nullptr, out);
    k_softmax<<<1, 1024>>>(out);                               // 9
}